// round 12
// baseline (speedup 1.0000x reference)
#include <cuda_runtime.h>
#include <cuda_fp16.h>
#include <math.h>
#include <stdint.h>

#define NB 2
#define NC 256
#define NS 32768
#define CTX 77
#define HEADS 8
#define JP 80
#define NP 640
#define M_TOTAL 65536
#define EPS 1e-5f
#define ATT_SCALE 0.17677669529663687f

// ---------------- scratch ----------------
__device__ float g_part[16 * 1024 * 2];
__device__ float g_stat[16][2];
__device__ float g_cn[NB * CTX * 768];
__device__ float g_v[NB * HEADS * CTX * 32];
__device__ __half g_wqt[NB * 256 * 256];
__device__ float g_qbias[NB * 256];
__device__ __half g_k2[NB * NP * 40];             // pads stay zero from static init
__device__ __half g_vw[NB * NC * NP];
__device__ __half g_xt[(size_t)M_TOTAL * NC];
__device__ __half g_p[(size_t)M_TOTAL * NP];

// ---------------- helpers ----------------
__device__ __forceinline__ uint32_t smem_u32(const void* p) {
    uint32_t a;
    asm("{ .reg .u64 t; cvta.to.shared.u64 t, %1; cvt.u32.u64 %0, t; }" : "=r"(a) : "l"(p));
    return a;
}
__device__ __forceinline__ void cp16(uint32_t dst, const void* src) {
    asm volatile("cp.async.ca.shared.global [%0], [%1], 16;" :: "r"(dst), "l"(src));
}
__device__ __forceinline__ void cp_commit() { asm volatile("cp.async.commit_group;" ::: "memory"); }
__device__ __forceinline__ void cp_wait0() { asm volatile("cp.async.wait_group 0;" ::: "memory"); }
__device__ __forceinline__ void cp_wait1() { asm volatile("cp.async.wait_group 1;" ::: "memory"); }

__device__ __forceinline__ void mma16(float* c, const uint32_t* a, uint32_t b0, uint32_t b1) {
    asm volatile("mma.sync.aligned.m16n8k16.row.col.f32.f16.f16.f32 "
                 "{%0,%1,%2,%3},{%4,%5,%6,%7},{%8,%9},{%0,%1,%2,%3};"
                 : "+f"(c[0]), "+f"(c[1]), "+f"(c[2]), "+f"(c[3])
                 : "r"(a[0]), "r"(a[1]), "r"(a[2]), "r"(a[3]), "r"(b0), "r"(b1));
}
__device__ __forceinline__ void ldsm4(uint32_t* r, uint32_t addr) {
    asm volatile("ldmatrix.sync.aligned.m8n8.x4.shared.b16 {%0,%1,%2,%3}, [%4];"
                 : "=r"(r[0]), "=r"(r[1]), "=r"(r[2]), "=r"(r[3]) : "r"(addr));
}

#define SH 40

// gemm1_fused smem layout (bytes)
#define OFF_A  0u
#define OFF_QT 67584u
#define OFF_KS 135168u
#define OFF_B0 186368u
#define OFF_B1 196608u
#define SMEM1  206848

// gemm2 smem layout (bytes): A=128x40h(10240), B=256x40h(20480), double buffered
#define G2_A0 0u
#define G2_B0 10240u
#define G2_A1 30720u
#define G2_B1 40960u
#define SMEM2 61440

// ---------------- xt_k ----------------
__global__ void xt_k(const float* __restrict__ x) {
    __shared__ float tl[32][33];
    __shared__ float red[8][2];
    int tx = threadIdx.x, ty = threadIdx.y;
    int s0 = blockIdx.x * 32, g = blockIdx.y, b = blockIdx.z;
    int c0 = g * 32;
    float s = 0.f, sq = 0.f;
#pragma unroll
    for (int i = ty; i < 32; i += 8) {
        float v = x[((size_t)b * 256 + c0 + i) * 32768 + s0 + tx];
        tl[i][tx] = v;
        s += v; sq += v * v;
    }
    __syncthreads();
#pragma unroll
    for (int i = ty; i < 32; i += 8)
        g_xt[((size_t)b * 32768 + s0 + i) * 256 + c0 + tx] = __float2half(tl[tx][i]);
#pragma unroll
    for (int o = 16; o; o >>= 1) {
        s += __shfl_xor_sync(0xffffffffu, s, o);
        sq += __shfl_xor_sync(0xffffffffu, sq, o);
    }
    if (tx == 0) { red[ty][0] = s; red[ty][1] = sq; }
    __syncthreads();
    if (tx == 0 && ty == 0) {
        float ts = 0.f, tq = 0.f;
#pragma unroll
        for (int i = 0; i < 8; i++) { ts += red[i][0]; tq += red[i][1]; }
        int idx = ((b * 8 + g) * 1024 + blockIdx.x) * 2;
        g_part[idx] = ts; g_part[idx + 1] = tq;
    }
}

__global__ void gn_final_k() {
    __shared__ float red[8][2];
    int gi = blockIdx.x, tid = threadIdx.x;
    float s = 0.f, sq = 0.f;
    for (int i = tid; i < 1024; i += 256) {
        float2 v = *(const float2*)&g_part[(gi * 1024 + i) * 2];
        s += v.x; sq += v.y;
    }
#pragma unroll
    for (int o = 16; o; o >>= 1) {
        s += __shfl_xor_sync(0xffffffffu, s, o);
        sq += __shfl_xor_sync(0xffffffffu, sq, o);
    }
    if ((tid & 31) == 0) { red[tid >> 5][0] = s; red[tid >> 5][1] = sq; }
    __syncthreads();
    if (tid == 0) {
        float ts = 0.f, tq = 0.f;
#pragma unroll
        for (int i = 0; i < 8; i++) { ts += red[i][0]; tq += red[i][1]; }
        const float inv = 1.f / 1048576.f;
        float mean = ts * inv;
        float var = tq * inv - mean * mean;
        g_stat[gi][0] = mean;
        g_stat[gi][1] = rsqrtf(var + EPS);
    }
}

// ---------------- context LayerNorm ----------------
__global__ void ctx_ln_k(const float* __restrict__ ctx, const float* __restrict__ lng,
                         const float* __restrict__ lnb) {
    __shared__ float red[8][2];
    __shared__ float smean, srstd;
    int row = blockIdx.x, tid = threadIdx.x;
    const float* cp = ctx + (size_t)row * 768;
    float v[3]; float s = 0.f, sq = 0.f;
#pragma unroll
    for (int i = 0; i < 3; i++) { v[i] = cp[tid + i * 256]; s += v[i]; sq += v[i] * v[i]; }
#pragma unroll
    for (int o = 16; o; o >>= 1) {
        s += __shfl_xor_sync(0xffffffffu, s, o);
        sq += __shfl_xor_sync(0xffffffffu, sq, o);
    }
    if ((tid & 31) == 0) { red[tid >> 5][0] = s; red[tid >> 5][1] = sq; }
    __syncthreads();
    if (tid == 0) {
        float ts = 0.f, tq = 0.f;
#pragma unroll
        for (int i = 0; i < 8; i++) { ts += red[i][0]; tq += red[i][1]; }
        float mean = ts * (1.f / 768.f);
        float var = tq * (1.f / 768.f) - mean * mean;
        smean = mean; srstd = rsqrtf(var + EPS);
    }
    __syncthreads();
    float mean = smean, rstd = srstd;
#pragma unroll
    for (int i = 0; i < 3; i++) {
        int idx = tid + i * 256;
        g_cn[(size_t)row * 768 + idx] = (v[i] - mean) * rstd * lng[idx] + lnb[idx];
    }
}

// ---------------- K,V projection ----------------
__global__ void kv_proj_k(const float* __restrict__ Wk, const float* __restrict__ Wv) {
    __shared__ float xnt[768 * 8];
    __shared__ float part[3][64][8];
    int tid = threadIdx.x;
    int isV = blockIdx.x >> 2, ct = blockIdx.x & 3;
    int row0 = blockIdx.y * 8;
    const float* W = isV ? Wv : Wk;
#pragma unroll
    for (int r = 0; r < 8; r++) {
        int row = row0 + r;
        for (int i = tid; i < 768; i += 256)
            xnt[i * 8 + r] = (row < 154) ? g_cn[(size_t)row * 768 + i] : 0.f;
    }
    __syncthreads();
    int c = tid & 63, ks = tid >> 6;
    int cg = ct * 64 + c;
    float acc[8];
#pragma unroll
    for (int r = 0; r < 8; r++) acc[r] = 0.f;
    int i0 = ks * 192;
#pragma unroll 8
    for (int i = i0; i < i0 + 192; i++) {
        float w = W[i * 256 + cg];
        float4 a0 = *(const float4*)&xnt[i * 8];
        float4 a1 = *(const float4*)&xnt[i * 8 + 4];
        acc[0] += a0.x * w; acc[1] += a0.y * w; acc[2] += a0.z * w; acc[3] += a0.w * w;
        acc[4] += a1.x * w; acc[5] += a1.y * w; acc[6] += a1.z * w; acc[7] += a1.w * w;
    }
    if (ks > 0) {
#pragma unroll
        for (int r = 0; r < 8; r++) part[ks - 1][c][r] = acc[r];
    }
    __syncthreads();
    if (ks == 0) {
#pragma unroll
        for (int r = 0; r < 8; r++)
            acc[r] += part[0][c][r] + part[1][c][r] + part[2][c][r];
        int h = cg >> 5, d = cg & 31;
#pragma unroll
        for (int r = 0; r < 8; r++) {
            int row = row0 + r;
            if (row < 154) {
                int b = row / 77, j = row % 77;
                if (isV) {
                    g_v[(((size_t)b * HEADS + h) * CTX + j) * 32 + d] = acc[r];
                } else {
                    g_k2[((size_t)b * NP + h * JP + j) * 40 + d] =
                        __float2half(acc[r] * ATT_SCALE);
                }
            }
        }
    }
}

// ---------------- wqt ----------------
__global__ void wqt_k(const float* __restrict__ Wq, const float* __restrict__ gng,
                      const float* __restrict__ gnb) {
    __shared__ float red[8];
    int n = blockIdx.x, b = blockIdx.y, c = threadIdx.x;
    int g = c >> 5;
    float mean = g_stat[b * 8 + g][0], rstd = g_stat[b * 8 + g][1];
    float ga = gng[c];
    float cA = rstd * ga;
    float cB = gnb[c] - mean * cA;
    float w = Wq[c * 256 + n];
    g_wqt[((size_t)b * 256 + n) * 256 + c] = __float2half(w * cA);
    float bc = cB * w;
#pragma unroll
    for (int o = 16; o; o >>= 1) bc += __shfl_xor_sync(0xffffffffu, bc, o);
    if ((c & 31) == 0) red[c >> 5] = bc;
    __syncthreads();
    if (c == 0) {
        float t = 0.f;
#pragma unroll
        for (int i = 0; i < 8; i++) t += red[i];
        g_qbias[b * 256 + n] = t;
    }
}

// ---------------- VW ----------------
__global__ void make_vw_k(const float* __restrict__ Wo) {
    int n = blockIdx.x, b = blockIdx.y, c = threadIdx.x;
    int h = n / JP, j = n % JP;
    __shared__ float vs[32];
    if (c < 32 && j < CTX) vs[c] = g_v[(((size_t)b * HEADS + h) * CTX + j) * 32 + c];
    __syncthreads();
    float acc = 0.f;
    if (j < CTX) {
#pragma unroll
        for (int d = 0; d < 32; d++) acc += vs[d] * Wo[(h * 32 + d) * 256 + c];
    }
    g_vw[((size_t)b * NC + c) * NP + n] = __float2half(acc);
}

// ---------------- gemm1_fused (512 threads, R11 proven) ----------------
__global__ void __launch_bounds__(512) gemm1_fused() {
    extern __shared__ char smem[];
    uint32_t sb = smem_u32(smem);
    int tid = threadIdx.x, lane = tid & 31, wid = tid >> 5;
    int grp = lane >> 2, lt4 = lane & 3;
    int row0 = blockIdx.x * 128;
    int b = row0 >> 15;

    const __half* Ag = g_xt + (size_t)row0 * 256;
    const __half* Wb = g_wqt + (size_t)b * 65536;
    const __half* Kb = g_k2 + (size_t)b * NP * 40;
    const float* biasb = g_qbias + b * 256;

    for (int id = tid; id < 4096; id += 512) {
        int r = id >> 5, c16 = id & 31;
        cp16(sb + OFF_A + (uint32_t)(r * 264 + c16 * 8) * 2, Ag + r * 256 + c16 * 8);
    }
    for (int id = tid; id < 3200; id += 512) {
        int r = id / 5, c16 = id % 5;
        cp16(sb + OFF_KS + (uint32_t)(r * 40 + c16 * 8) * 2, Kb + r * 40 + c16 * 8);
    }
    cp_commit();

    int smr = tid >> 2, sseg = (tid & 3) * 8;
    uint32_t dstoff = (uint32_t)(smr * 40 + sseg) * 2u;
    auto stageB = [&](int gi) {
        int half = gi >> 3, ki = gi & 7;
        const __half* src = Wb + (size_t)(half * 128 + smr) * 256 + ki * 32 + sseg;
        cp16(sb + ((gi & 1) ? OFF_B1 : OFF_B0) + dstoff, src);
        cp_commit();
    };
    stageB(0);

    int wm0 = (wid & 3) * 32, wn0 = (wid >> 2) * 32;
    uint32_t lrow = (uint32_t)(lane & 15);
    uint32_t lcol = (uint32_t)((lane >> 4) << 3);
    uint32_t aoffb[2], boff1[2];
#pragma unroll
    for (int mf = 0; mf < 2; mf++)
        aoffb[mf] = ((wm0 + mf * 16 + lrow) * 264 + lcol) * 2u;
#pragma unroll
    for (int nfp = 0; nfp < 2; nfp++)
        boff1[nfp] = ((wn0 + nfp * 16 + lrow) * 40 + lcol) * 2u;

    float acc[2][4][4];
#pragma unroll
    for (int a = 0; a < 2; a++)
#pragma unroll
        for (int c = 0; c < 4; c++)
#pragma unroll
            for (int e = 0; e < 4; e++) acc[a][c][e] = 0.f;

    for (int half = 0; half < 2; half++) {
        for (int ki = 0; ki < 8; ki++) {
            int gi = half * 8 + ki;
            if (gi + 1 < 16) { stageB(gi + 1); cp_wait1(); } else cp_wait0();
            __syncthreads();
            uint32_t bB = sb + ((gi & 1) ? OFF_B1 : OFF_B0);
#pragma unroll
            for (int kk = 0; kk < 32; kk += 16) {
                uint32_t af[2][4], bbf[2][4];
#pragma unroll
                for (int mf = 0; mf < 2; mf++)
                    ldsm4(af[mf], sb + OFF_A + aoffb[mf] + (ki * 32 + kk) * 2);
#pragma unroll
                for (int nfp = 0; nfp < 2; nfp++)
                    ldsm4(bbf[nfp], bB + boff1[nfp] + kk * 2);
#pragma unroll
                for (int nf = 0; nf < 4; nf++) {
                    uint32_t b0 = bbf[nf >> 1][nf & 1], b1 = bbf[nf >> 1][2 + (nf & 1)];
#pragma unroll
                    for (int mf = 0; mf < 2; mf++) mma16(acc[mf][nf], af[mf], b0, b1);
                }
            }
            __syncthreads();
        }
        int nh = half * 128;
#pragma unroll
        for (int mf = 0; mf < 2; mf++) {
            int r0 = wm0 + mf * 16 + grp;
#pragma unroll
            for (int nf = 0; nf < 4; nf++) {
                int col = nh + wn0 + nf * 8 + 2 * lt4;
                float2 bv = *(const float2*)(biasb + col);
                __half2 h0 = __floats2half2_rn(acc[mf][nf][0] + bv.x, acc[mf][nf][1] + bv.y);
                __half2 h1 = __floats2half2_rn(acc[mf][nf][2] + bv.x, acc[mf][nf][3] + bv.y);
                *(uint32_t*)(smem + OFF_QT + (uint32_t)(r0 * 264 + col) * 2) = *(uint32_t*)&h0;
                *(uint32_t*)(smem + OFF_QT + (uint32_t)((r0 + 8) * 264 + col) * 2) = *(uint32_t*)&h1;
                acc[mf][nf][0] = acc[mf][nf][1] = acc[mf][nf][2] = acc[mf][nf][3] = 0.f;
            }
        }
    }
    __syncthreads();

    int wm2 = (wid & 3) * 32;
    float acc2[2][10][4];
#pragma unroll 1
    for (int it = 0; it < 2; it++) {
        int h = it * 4 + (wid >> 2);
        uint32_t aoff2[2], boff2[5];
#pragma unroll
        for (int mf = 0; mf < 2; mf++)
            aoff2[mf] = ((wm2 + mf * 16 + lrow) * 264 + h * 32 + lcol) * 2u;
#pragma unroll
        for (int nfp = 0; nfp < 5; nfp++)
            boff2[nfp] = ((h * 80 + nfp * 16 + lrow) * 40 + lcol) * 2u;
#pragma unroll
        for (int a = 0; a < 2; a++)
#pragma unroll
            for (int c = 0; c < 10; c++)
#pragma unroll
                for (int e = 0; e < 4; e++) acc2[a][c][e] = 0.f;
#pragma unroll
        for (int kk = 0; kk < 32; kk += 16) {
            uint32_t af[2][4], bbf[5][4];
#pragma unroll
            for (int mf = 0; mf < 2; mf++)
                ldsm4(af[mf], sb + OFF_QT + aoff2[mf] + kk * 2);
#pragma unroll
            for (int nfp = 0; nfp < 5; nfp++)
                ldsm4(bbf[nfp], sb + OFF_KS + boff2[nfp] + kk * 2);
#pragma unroll
            for (int nf = 0; nf < 10; nf++) {
                uint32_t b0 = bbf[nf >> 1][nf & 1], b1 = bbf[nf >> 1][2 + (nf & 1)];
#pragma unroll
                for (int mf = 0; mf < 2; mf++) mma16(acc2[mf][nf], af[mf], b0, b1);
            }
        }
#pragma unroll
        for (int mf = 0; mf < 2; mf++) {
#pragma unroll
            for (int rh = 0; rh < 2; rh++) {
                int row = wm2 + mf * 16 + grp + rh * 8;
                float m = -1e30f;
#pragma unroll
                for (int nf = 0; nf < 10; nf++) {
#pragma unroll
                    for (int e = 0; e < 2; e++) {
                        int j = nf * 8 + 2 * lt4 + e;
                        float v = (j < CTX) ? acc2[mf][nf][rh * 2 + e] : -1e30f;
                        acc2[mf][nf][rh * 2 + e] = v;
                        m = fmaxf(m, v);
                    }
                }
                m = fmaxf(m, __shfl_xor_sync(0xffffffffu, m, 1));
                m = fmaxf(m, __shfl_xor_sync(0xffffffffu, m, 2));
                float s = 0.f;
#pragma unroll
                for (int nf = 0; nf < 10; nf++) {
#pragma unroll
                    for (int e = 0; e < 2; e++) {
                        int j = nf * 8 + 2 * lt4 + e;
                        float ev = (j < CTX) ? __expf(acc2[mf][nf][rh * 2 + e] - m) : 0.f;
                        acc2[mf][nf][rh * 2 + e] = ev;
                        s += ev;
                    }
                }
                s += __shfl_xor_sync(0xffffffffu, s, 1);
                s += __shfl_xor_sync(0xffffffffu, s, 2);
                float inv = 1.f / s;
                __half* pr = g_p + (size_t)(row0 + row) * NP + h * 80 + 2 * lt4;
#pragma unroll
                for (int nf = 0; nf < 10; nf++) {
                    __half2 hv = __floats2half2_rn(acc2[mf][nf][rh * 2] * inv,
                                                   acc2[mf][nf][rh * 2 + 1] * inv);
                    *(__half2*)(pr + nf * 8) = hv;
                }
            }
        }
    }
}

// ---------------- GEMM2 (512 threads, full N=256): out = g_p @ vw^T + bo + x ----------------
__global__ void __launch_bounds__(512) gemm2_mma(const float* __restrict__ x,
                                                 const float* __restrict__ bo,
                                                 float* __restrict__ out) {
    extern __shared__ char smem[];
    uint32_t sb = smem_u32(smem);
    int tid = threadIdx.x, lane = tid & 31, wid = tid >> 5;   // wid 0..15
    int grp = lane >> 2, lt4 = lane & 3;
    int wm0 = (wid & 1) * 64, wn0 = (wid >> 1) * 32;          // 2m x 8n
    int row0 = blockIdx.x * 128;
    int b = row0 >> 15, s0 = row0 & 32767;

    const __half* Ag = g_p + (size_t)row0 * NP;
    const __half* Bg = g_vw + (size_t)b * NC * NP;

    // staging: A rows via tid>>2 (one 16B chunk), B rows via tid>>1 (two 16B chunks)
    int amr = tid >> 2, aseg = (tid & 3) * 8;
    uint32_t adst = (uint32_t)(amr * 40 + aseg) * 2u;
    int bmr = tid >> 1, bseg = (tid & 1) * 16;
    uint32_t bdst = (uint32_t)(bmr * 40 + bseg) * 2u;

    auto stage = [&](int ki, int buf) {
        const __half* a = Ag + (size_t)amr * NP + ki * 32 + aseg;
        cp16(sb + (buf ? G2_A1 : G2_A0) + adst, a);
        const __half* bp = Bg + (size_t)bmr * NP + ki * 32 + bseg;
        uint32_t bb = sb + (buf ? G2_B1 : G2_B0) + bdst;
        cp16(bb, bp);
        cp16(bb + 16, bp + 8);
        cp_commit();
    };

    uint32_t lrow = (uint32_t)(lane & 15);
    uint32_t lcol = (uint32_t)((lane >> 4) << 3);
    uint32_t aoff[4], boff[2];
#pragma unroll
    for (int mf = 0; mf < 4; mf++)
        aoff[mf] = ((wm0 + mf * 16 + lrow) * 40 + lcol) * 2u;
#pragma unroll
    for (int nfp = 0; nfp < 2; nfp++)
        boff[nfp] = ((wn0 + nfp * 16 + lrow) * 40 + lcol) * 2u;

    float acc[4][4][4];
#pragma unroll
    for (int a = 0; a < 4; a++)
#pragma unroll
        for (int c = 0; c < 4; c++)
#pragma unroll
            for (int e = 0; e < 4; e++) acc[a][c][e] = 0.f;

    stage(0, 0);
    const int NK = 20;
    for (int ki = 0; ki < NK; ki++) {
        int cur = ki & 1;
        if (ki + 1 < NK) { stage(ki + 1, cur ^ 1); cp_wait1(); } else { cp_wait0(); }
        __syncthreads();
        uint32_t bA = sb + (cur ? G2_A1 : G2_A0), bB = sb + (cur ? G2_B1 : G2_B0);
#pragma unroll
        for (int kk = 0; kk < 32; kk += 16) {
            uint32_t af[4][4], bbf[2][4];
#pragma unroll
            for (int mf = 0; mf < 4; mf++) ldsm4(af[mf], bA + aoff[mf] + kk * 2);
#pragma unroll
            for (int nfp = 0; nfp < 2; nfp++) ldsm4(bbf[nfp], bB + boff[nfp] + kk * 2);
#pragma unroll
            for (int nf = 0; nf < 4; nf++) {
                uint32_t b0 = bbf[nf >> 1][nf & 1], b1 = bbf[nf >> 1][2 + (nf & 1)];
#pragma unroll
                for (int mf = 0; mf < 4; mf++) mma16(acc[mf][nf], af[mf], b0, b1);
            }
        }
        __syncthreads();
    }

    // epilogue: 4 passes (rowhalf x colhalf), 64 rows x 128 cols bounce (stride 68)
    float* bounce = (float*)smem;
#pragma unroll
    for (int rh = 0; rh < 2; rh++) {
#pragma unroll
        for (int ch = 0; ch < 2; ch++) {
            if ((wid & 1) == rh && (wid >> 1) >= ch * 4 && (wid >> 1) < ch * 4 + 4) {
                int cn0 = wn0 - ch * 128;    // local col base 0..96
#pragma unroll
                for (int mf = 0; mf < 4; mf++) {
                    int r = mf * 16 + grp;   // local row 0..63
#pragma unroll
                    for (int nf = 0; nf < 4; nf++) {
                        int c = cn0 + nf * 8 + 2 * lt4;
                        bounce[(c + 0) * 68 + r] = acc[mf][nf][0];
                        bounce[(c + 1) * 68 + r] = acc[mf][nf][1];
                        bounce[(c + 0) * 68 + r + 8] = acc[mf][nf][2];
                        bounce[(c + 1) * 68 + r + 8] = acc[mf][nf][3];
                    }
                }
            }
            __syncthreads();
#pragma unroll
            for (int p = 0; p < 4; p++) {
                int cl = p * 32 + (tid >> 4);     // local col 0..127
                int sl = (tid & 15) * 4;          // local row 0..60
                int cg = ch * 128 + cl;
                float4 v = *(const float4*)&bounce[cl * 68 + sl];
                size_t idx = ((size_t)b * 256 + cg) * 32768 + s0 + rh * 64 + sl;
                float4 xv = *(const float4*)(x + idx);
                float bb2 = bo[cg];
                v.x += xv.x + bb2; v.y += xv.y + bb2; v.z += xv.z + bb2; v.w += xv.w + bb2;
                *(float4*)(out + idx) = v;
            }
            __syncthreads();
        }
    }
}

// ---------------- launch ----------------
extern "C" void kernel_launch(void* const* d_in, const int* in_sizes, int n_in,
                              void* d_out, int out_size) {
    const float* x   = (const float*)d_in[0];
    const float* ctx = (const float*)d_in[1];
    const float* gng = (const float*)d_in[2];
    const float* gnb = (const float*)d_in[3];
    const float* lng = (const float*)d_in[4];
    const float* lnb = (const float*)d_in[5];
    const float* Wq  = (const float*)d_in[6];
    const float* Wk  = (const float*)d_in[7];
    const float* Wv  = (const float*)d_in[8];
    const float* Wo  = (const float*)d_in[9];
    const float* bo  = (const float*)d_in[10];
    float* out = (float*)d_out;

    cudaFuncSetAttribute(gemm1_fused, cudaFuncAttributeMaxDynamicSharedMemorySize, SMEM1);
    cudaFuncSetAttribute(gemm2_mma, cudaFuncAttributeMaxDynamicSharedMemorySize, SMEM2);

    xt_k<<<dim3(1024, 8, 2), dim3(32, 8)>>>(x);
    gn_final_k<<<16, 256>>>();
    ctx_ln_k<<<154, 256>>>(ctx, lng, lnb);
    kv_proj_k<<<dim3(8, 20), 256>>>(Wk, Wv);
    make_vw_k<<<dim3(NP, NB), 256>>>(Wo);
    wqt_k<<<dim3(256, 2), 256>>>(Wq, gng, gnb);
    gemm1_fused<<<512, 512, SMEM1>>>();
    gemm2_mma<<<512, 512, SMEM2>>>(x, bo, out);
}

// round 13
// speedup vs baseline: 1.0729x; 1.0729x over previous
#include <cuda_runtime.h>
#include <cuda_fp16.h>
#include <math.h>
#include <stdint.h>

#define NB 2
#define NC 256
#define NS 32768
#define CTX 77
#define HEADS 8
#define JP 80
#define NP 640
#define M_TOTAL 65536
#define EPS 1e-5f
#define ATT_SCALE 0.17677669529663687f

// ---------------- scratch ----------------
__device__ float g_part[16 * 1024 * 2];
__device__ float g_stat[16][2];
__device__ float g_cn[NB * CTX * 768];
__device__ float g_v[NB * HEADS * CTX * 32];
__device__ __half g_wqt[NB * 256 * 256];
__device__ float g_qbias[NB * 256];
__device__ __half g_k2[NB * NP * 40];             // pads stay zero from static init
__device__ __half g_vw[NB * NC * NP];
__device__ __half g_xt[(size_t)M_TOTAL * NC];
__device__ __half g_p[(size_t)M_TOTAL * NP];

// ---------------- helpers ----------------
__device__ __forceinline__ uint32_t smem_u32(const void* p) {
    uint32_t a;
    asm("{ .reg .u64 t; cvta.to.shared.u64 t, %1; cvt.u32.u64 %0, t; }" : "=r"(a) : "l"(p));
    return a;
}
__device__ __forceinline__ void cp16(uint32_t dst, const void* src) {
    asm volatile("cp.async.ca.shared.global [%0], [%1], 16;" :: "r"(dst), "l"(src));
}
__device__ __forceinline__ void cp_commit() { asm volatile("cp.async.commit_group;" ::: "memory"); }
__device__ __forceinline__ void cp_wait0() { asm volatile("cp.async.wait_group 0;" ::: "memory"); }
__device__ __forceinline__ void cp_wait1() { asm volatile("cp.async.wait_group 1;" ::: "memory"); }

__device__ __forceinline__ void mma16(float* c, const uint32_t* a, uint32_t b0, uint32_t b1) {
    asm volatile("mma.sync.aligned.m16n8k16.row.col.f32.f16.f16.f32 "
                 "{%0,%1,%2,%3},{%4,%5,%6,%7},{%8,%9},{%0,%1,%2,%3};"
                 : "+f"(c[0]), "+f"(c[1]), "+f"(c[2]), "+f"(c[3])
                 : "r"(a[0]), "r"(a[1]), "r"(a[2]), "r"(a[3]), "r"(b0), "r"(b1));
}
__device__ __forceinline__ void ldsm4(uint32_t* r, uint32_t addr) {
    asm volatile("ldmatrix.sync.aligned.m8n8.x4.shared.b16 {%0,%1,%2,%3}, [%4];"
                 : "=r"(r[0]), "=r"(r[1]), "=r"(r[2]), "=r"(r[3]) : "r"(addr));
}

#define SH 40

// gemm1_fused smem layout (bytes)
#define OFF_A  0u
#define OFF_QT 67584u
#define OFF_KS 135168u
#define OFF_B0 186368u
#define OFF_B1 196608u
#define SMEM1  206848

// gemm2 smem (K-tile 64, stride 72 halves): tiles 128x72x2 = 18432 B
#define G2T 18432u
#define SMEM2 (4 * 18432)

// ---------------- xt_k ----------------
__global__ void xt_k(const float* __restrict__ x) {
    __shared__ float tl[32][33];
    __shared__ float red[8][2];
    int tx = threadIdx.x, ty = threadIdx.y;
    int s0 = blockIdx.x * 32, g = blockIdx.y, b = blockIdx.z;
    int c0 = g * 32;
    float s = 0.f, sq = 0.f;
#pragma unroll
    for (int i = ty; i < 32; i += 8) {
        float v = x[((size_t)b * 256 + c0 + i) * 32768 + s0 + tx];
        tl[i][tx] = v;
        s += v; sq += v * v;
    }
    __syncthreads();
#pragma unroll
    for (int i = ty; i < 32; i += 8)
        g_xt[((size_t)b * 32768 + s0 + i) * 256 + c0 + tx] = __float2half(tl[tx][i]);
#pragma unroll
    for (int o = 16; o; o >>= 1) {
        s += __shfl_xor_sync(0xffffffffu, s, o);
        sq += __shfl_xor_sync(0xffffffffu, sq, o);
    }
    if (tx == 0) { red[ty][0] = s; red[ty][1] = sq; }
    __syncthreads();
    if (tx == 0 && ty == 0) {
        float ts = 0.f, tq = 0.f;
#pragma unroll
        for (int i = 0; i < 8; i++) { ts += red[i][0]; tq += red[i][1]; }
        int idx = ((b * 8 + g) * 1024 + blockIdx.x) * 2;
        g_part[idx] = ts; g_part[idx + 1] = tq;
    }
}

__global__ void gn_final_k() {
    __shared__ float red[8][2];
    int gi = blockIdx.x, tid = threadIdx.x;
    float s = 0.f, sq = 0.f;
    for (int i = tid; i < 1024; i += 256) {
        float2 v = *(const float2*)&g_part[(gi * 1024 + i) * 2];
        s += v.x; sq += v.y;
    }
#pragma unroll
    for (int o = 16; o; o >>= 1) {
        s += __shfl_xor_sync(0xffffffffu, s, o);
        sq += __shfl_xor_sync(0xffffffffu, sq, o);
    }
    if ((tid & 31) == 0) { red[tid >> 5][0] = s; red[tid >> 5][1] = sq; }
    __syncthreads();
    if (tid == 0) {
        float ts = 0.f, tq = 0.f;
#pragma unroll
        for (int i = 0; i < 8; i++) { ts += red[i][0]; tq += red[i][1]; }
        const float inv = 1.f / 1048576.f;
        float mean = ts * inv;
        float var = tq * inv - mean * mean;
        g_stat[gi][0] = mean;
        g_stat[gi][1] = rsqrtf(var + EPS);
    }
}

// ---------------- context LayerNorm ----------------
__global__ void ctx_ln_k(const float* __restrict__ ctx, const float* __restrict__ lng,
                         const float* __restrict__ lnb) {
    __shared__ float red[8][2];
    __shared__ float smean, srstd;
    int row = blockIdx.x, tid = threadIdx.x;
    const float* cp = ctx + (size_t)row * 768;
    float v[3]; float s = 0.f, sq = 0.f;
#pragma unroll
    for (int i = 0; i < 3; i++) { v[i] = cp[tid + i * 256]; s += v[i]; sq += v[i] * v[i]; }
#pragma unroll
    for (int o = 16; o; o >>= 1) {
        s += __shfl_xor_sync(0xffffffffu, s, o);
        sq += __shfl_xor_sync(0xffffffffu, sq, o);
    }
    if ((tid & 31) == 0) { red[tid >> 5][0] = s; red[tid >> 5][1] = sq; }
    __syncthreads();
    if (tid == 0) {
        float ts = 0.f, tq = 0.f;
#pragma unroll
        for (int i = 0; i < 8; i++) { ts += red[i][0]; tq += red[i][1]; }
        float mean = ts * (1.f / 768.f);
        float var = tq * (1.f / 768.f) - mean * mean;
        smean = mean; srstd = rsqrtf(var + EPS);
    }
    __syncthreads();
    float mean = smean, rstd = srstd;
#pragma unroll
    for (int i = 0; i < 3; i++) {
        int idx = tid + i * 256;
        g_cn[(size_t)row * 768 + idx] = (v[i] - mean) * rstd * lng[idx] + lnb[idx];
    }
}

// ---------------- K,V projection ----------------
__global__ void kv_proj_k(const float* __restrict__ Wk, const float* __restrict__ Wv) {
    __shared__ float xnt[768 * 8];
    __shared__ float part[3][64][8];
    int tid = threadIdx.x;
    int isV = blockIdx.x >> 2, ct = blockIdx.x & 3;
    int row0 = blockIdx.y * 8;
    const float* W = isV ? Wv : Wk;
#pragma unroll
    for (int r = 0; r < 8; r++) {
        int row = row0 + r;
        for (int i = tid; i < 768; i += 256)
            xnt[i * 8 + r] = (row < 154) ? g_cn[(size_t)row * 768 + i] : 0.f;
    }
    __syncthreads();
    int c = tid & 63, ks = tid >> 6;
    int cg = ct * 64 + c;
    float acc[8];
#pragma unroll
    for (int r = 0; r < 8; r++) acc[r] = 0.f;
    int i0 = ks * 192;
#pragma unroll 8
    for (int i = i0; i < i0 + 192; i++) {
        float w = W[i * 256 + cg];
        float4 a0 = *(const float4*)&xnt[i * 8];
        float4 a1 = *(const float4*)&xnt[i * 8 + 4];
        acc[0] += a0.x * w; acc[1] += a0.y * w; acc[2] += a0.z * w; acc[3] += a0.w * w;
        acc[4] += a1.x * w; acc[5] += a1.y * w; acc[6] += a1.z * w; acc[7] += a1.w * w;
    }
    if (ks > 0) {
#pragma unroll
        for (int r = 0; r < 8; r++) part[ks - 1][c][r] = acc[r];
    }
    __syncthreads();
    if (ks == 0) {
#pragma unroll
        for (int r = 0; r < 8; r++)
            acc[r] += part[0][c][r] + part[1][c][r] + part[2][c][r];
        int h = cg >> 5, d = cg & 31;
#pragma unroll
        for (int r = 0; r < 8; r++) {
            int row = row0 + r;
            if (row < 154) {
                int b = row / 77, j = row % 77;
                if (isV) {
                    g_v[(((size_t)b * HEADS + h) * CTX + j) * 32 + d] = acc[r];
                } else {
                    g_k2[((size_t)b * NP + h * JP + j) * 40 + d] =
                        __float2half(acc[r] * ATT_SCALE);
                }
            }
        }
    }
}

// ---------------- wqt ----------------
__global__ void wqt_k(const float* __restrict__ Wq, const float* __restrict__ gng,
                      const float* __restrict__ gnb) {
    __shared__ float red[8];
    int n = blockIdx.x, b = blockIdx.y, c = threadIdx.x;
    int g = c >> 5;
    float mean = g_stat[b * 8 + g][0], rstd = g_stat[b * 8 + g][1];
    float ga = gng[c];
    float cA = rstd * ga;
    float cB = gnb[c] - mean * cA;
    float w = Wq[c * 256 + n];
    g_wqt[((size_t)b * 256 + n) * 256 + c] = __float2half(w * cA);
    float bc = cB * w;
#pragma unroll
    for (int o = 16; o; o >>= 1) bc += __shfl_xor_sync(0xffffffffu, bc, o);
    if ((c & 31) == 0) red[c >> 5] = bc;
    __syncthreads();
    if (c == 0) {
        float t = 0.f;
#pragma unroll
        for (int i = 0; i < 8; i++) t += red[i];
        g_qbias[b * 256 + n] = t;
    }
}

// ---------------- VW ----------------
__global__ void make_vw_k(const float* __restrict__ Wo) {
    int n = blockIdx.x, b = blockIdx.y, c = threadIdx.x;
    int h = n / JP, j = n % JP;
    __shared__ float vs[32];
    if (c < 32 && j < CTX) vs[c] = g_v[(((size_t)b * HEADS + h) * CTX + j) * 32 + c];
    __syncthreads();
    float acc = 0.f;
    if (j < CTX) {
#pragma unroll
        for (int d = 0; d < 32; d++) acc += vs[d] * Wo[(h * 32 + d) * 256 + c];
    }
    g_vw[((size_t)b * NC + c) * NP + n] = __float2half(acc);
}

// ---------------- gemm1_fused (512 threads, R11 proven) ----------------
__global__ void __launch_bounds__(512) gemm1_fused() {
    extern __shared__ char smem[];
    uint32_t sb = smem_u32(smem);
    int tid = threadIdx.x, lane = tid & 31, wid = tid >> 5;
    int grp = lane >> 2, lt4 = lane & 3;
    int row0 = blockIdx.x * 128;
    int b = row0 >> 15;

    const __half* Ag = g_xt + (size_t)row0 * 256;
    const __half* Wb = g_wqt + (size_t)b * 65536;
    const __half* Kb = g_k2 + (size_t)b * NP * 40;
    const float* biasb = g_qbias + b * 256;

    for (int id = tid; id < 4096; id += 512) {
        int r = id >> 5, c16 = id & 31;
        cp16(sb + OFF_A + (uint32_t)(r * 264 + c16 * 8) * 2, Ag + r * 256 + c16 * 8);
    }
    for (int id = tid; id < 3200; id += 512) {
        int r = id / 5, c16 = id % 5;
        cp16(sb + OFF_KS + (uint32_t)(r * 40 + c16 * 8) * 2, Kb + r * 40 + c16 * 8);
    }
    cp_commit();

    int smr = tid >> 2, sseg = (tid & 3) * 8;
    uint32_t dstoff = (uint32_t)(smr * 40 + sseg) * 2u;
    auto stageB = [&](int gi) {
        int half = gi >> 3, ki = gi & 7;
        const __half* src = Wb + (size_t)(half * 128 + smr) * 256 + ki * 32 + sseg;
        cp16(sb + ((gi & 1) ? OFF_B1 : OFF_B0) + dstoff, src);
        cp_commit();
    };
    stageB(0);

    int wm0 = (wid & 3) * 32, wn0 = (wid >> 2) * 32;
    uint32_t lrow = (uint32_t)(lane & 15);
    uint32_t lcol = (uint32_t)((lane >> 4) << 3);
    uint32_t aoffb[2], boff1[2];
#pragma unroll
    for (int mf = 0; mf < 2; mf++)
        aoffb[mf] = ((wm0 + mf * 16 + lrow) * 264 + lcol) * 2u;
#pragma unroll
    for (int nfp = 0; nfp < 2; nfp++)
        boff1[nfp] = ((wn0 + nfp * 16 + lrow) * 40 + lcol) * 2u;

    float acc[2][4][4];
#pragma unroll
    for (int a = 0; a < 2; a++)
#pragma unroll
        for (int c = 0; c < 4; c++)
#pragma unroll
            for (int e = 0; e < 4; e++) acc[a][c][e] = 0.f;

    for (int half = 0; half < 2; half++) {
        for (int ki = 0; ki < 8; ki++) {
            int gi = half * 8 + ki;
            if (gi + 1 < 16) { stageB(gi + 1); cp_wait1(); } else cp_wait0();
            __syncthreads();
            uint32_t bB = sb + ((gi & 1) ? OFF_B1 : OFF_B0);
#pragma unroll
            for (int kk = 0; kk < 32; kk += 16) {
                uint32_t af[2][4], bbf[2][4];
#pragma unroll
                for (int mf = 0; mf < 2; mf++)
                    ldsm4(af[mf], sb + OFF_A + aoffb[mf] + (ki * 32 + kk) * 2);
#pragma unroll
                for (int nfp = 0; nfp < 2; nfp++)
                    ldsm4(bbf[nfp], bB + boff1[nfp] + kk * 2);
#pragma unroll
                for (int nf = 0; nf < 4; nf++) {
                    uint32_t b0 = bbf[nf >> 1][nf & 1], b1 = bbf[nf >> 1][2 + (nf & 1)];
#pragma unroll
                    for (int mf = 0; mf < 2; mf++) mma16(acc[mf][nf], af[mf], b0, b1);
                }
            }
            __syncthreads();
        }
        int nh = half * 128;
#pragma unroll
        for (int mf = 0; mf < 2; mf++) {
            int r0 = wm0 + mf * 16 + grp;
#pragma unroll
            for (int nf = 0; nf < 4; nf++) {
                int col = nh + wn0 + nf * 8 + 2 * lt4;
                float2 bv = *(const float2*)(biasb + col);
                __half2 h0 = __floats2half2_rn(acc[mf][nf][0] + bv.x, acc[mf][nf][1] + bv.y);
                __half2 h1 = __floats2half2_rn(acc[mf][nf][2] + bv.x, acc[mf][nf][3] + bv.y);
                *(uint32_t*)(smem + OFF_QT + (uint32_t)(r0 * 264 + col) * 2) = *(uint32_t*)&h0;
                *(uint32_t*)(smem + OFF_QT + (uint32_t)((r0 + 8) * 264 + col) * 2) = *(uint32_t*)&h1;
                acc[mf][nf][0] = acc[mf][nf][1] = acc[mf][nf][2] = acc[mf][nf][3] = 0.f;
            }
        }
    }
    __syncthreads();

    int wm2 = (wid & 3) * 32;
    float acc2[2][10][4];
#pragma unroll 1
    for (int it = 0; it < 2; it++) {
        int h = it * 4 + (wid >> 2);
        uint32_t aoff2[2], boff2[5];
#pragma unroll
        for (int mf = 0; mf < 2; mf++)
            aoff2[mf] = ((wm2 + mf * 16 + lrow) * 264 + h * 32 + lcol) * 2u;
#pragma unroll
        for (int nfp = 0; nfp < 5; nfp++)
            boff2[nfp] = ((h * 80 + nfp * 16 + lrow) * 40 + lcol) * 2u;
#pragma unroll
        for (int a = 0; a < 2; a++)
#pragma unroll
            for (int c = 0; c < 10; c++)
#pragma unroll
                for (int e = 0; e < 4; e++) acc2[a][c][e] = 0.f;
#pragma unroll
        for (int kk = 0; kk < 32; kk += 16) {
            uint32_t af[2][4], bbf[5][4];
#pragma unroll
            for (int mf = 0; mf < 2; mf++)
                ldsm4(af[mf], sb + OFF_QT + aoff2[mf] + kk * 2);
#pragma unroll
            for (int nfp = 0; nfp < 5; nfp++)
                ldsm4(bbf[nfp], sb + OFF_KS + boff2[nfp] + kk * 2);
#pragma unroll
            for (int nf = 0; nf < 10; nf++) {
                uint32_t b0 = bbf[nf >> 1][nf & 1], b1 = bbf[nf >> 1][2 + (nf & 1)];
#pragma unroll
                for (int mf = 0; mf < 2; mf++) mma16(acc2[mf][nf], af[mf], b0, b1);
            }
        }
#pragma unroll
        for (int mf = 0; mf < 2; mf++) {
#pragma unroll
            for (int rh = 0; rh < 2; rh++) {
                int row = wm2 + mf * 16 + grp + rh * 8;
                float m = -1e30f;
#pragma unroll
                for (int nf = 0; nf < 10; nf++) {
#pragma unroll
                    for (int e = 0; e < 2; e++) {
                        int j = nf * 8 + 2 * lt4 + e;
                        float v = (j < CTX) ? acc2[mf][nf][rh * 2 + e] : -1e30f;
                        acc2[mf][nf][rh * 2 + e] = v;
                        m = fmaxf(m, v);
                    }
                }
                m = fmaxf(m, __shfl_xor_sync(0xffffffffu, m, 1));
                m = fmaxf(m, __shfl_xor_sync(0xffffffffu, m, 2));
                float s = 0.f;
#pragma unroll
                for (int nf = 0; nf < 10; nf++) {
#pragma unroll
                    for (int e = 0; e < 2; e++) {
                        int j = nf * 8 + 2 * lt4 + e;
                        float ev = (j < CTX) ? __expf(acc2[mf][nf][rh * 2 + e] - m) : 0.f;
                        acc2[mf][nf][rh * 2 + e] = ev;
                        s += ev;
                    }
                }
                s += __shfl_xor_sync(0xffffffffu, s, 1);
                s += __shfl_xor_sync(0xffffffffu, s, 2);
                float inv = 1.f / s;
                __half* pr = g_p + (size_t)(row0 + row) * NP + h * 80 + 2 * lt4;
#pragma unroll
                for (int nf = 0; nf < 10; nf++) {
                    __half2 hv = __floats2half2_rn(acc2[mf][nf][rh * 2] * inv,
                                                   acc2[mf][nf][rh * 2 + 1] * inv);
                    *(__half2*)(pr + nf * 8) = hv;
                }
            }
        }
    }
}

// ---------------- GEMM2 (K-tile 64): out = g_p @ vw^T + bo + x ----------------
__global__ void __launch_bounds__(256, 2) gemm2_mma(const float* __restrict__ x,
                                                    const float* __restrict__ bo,
                                                    float* __restrict__ out) {
    extern __shared__ char smem[];
    uint32_t sb = smem_u32(smem);
    int tid = threadIdx.x, lane = tid & 31, wid = tid >> 5;
    int grp = lane >> 2, lt4 = lane & 3;
    int wm0 = (wid & 1) * 64, wn0 = (wid >> 1) * 32;
    int n0 = blockIdx.x * 128;
    int row0 = blockIdx.y * 128;
    int b = row0 >> 15, s0 = row0 & 32767;

    const uint32_t offA[2] = {0u, 2u * G2T};
    const uint32_t offB[2] = {G2T, 3u * G2T};

    const __half* Ag = g_p + (size_t)row0 * NP;
    const __half* Bg = g_vw + ((size_t)b * NC + n0) * NP;

    int sm = tid >> 1;
    int so = (tid & 1) * 32;                       // half-offset 0 or 32
    uint32_t dstoff = (uint32_t)(sm * 72 + so) * 2u;

    auto stage = [&](int ki, int buf) {
        const __half* a = Ag + (size_t)sm * NP + ki * 64 + so;
        uint32_t da = sb + offA[buf] + dstoff;
        cp16(da, a);  cp16(da + 16, a + 8);  cp16(da + 32, a + 16);  cp16(da + 48, a + 24);
        const __half* bp = Bg + (size_t)sm * NP + ki * 64 + so;
        uint32_t db = sb + offB[buf] + dstoff;
        cp16(db, bp); cp16(db + 16, bp + 8); cp16(db + 32, bp + 16); cp16(db + 48, bp + 24);
        cp_commit();
    };

    uint32_t lrow = (uint32_t)(lane & 15);
    uint32_t lcol = (uint32_t)((lane >> 4) << 3);
    uint32_t aoff[4], boff[2];
#pragma unroll
    for (int mf = 0; mf < 4; mf++)
        aoff[mf] = ((wm0 + mf * 16 + lrow) * 72 + lcol) * 2u;
#pragma unroll
    for (int nfp = 0; nfp < 2; nfp++)
        boff[nfp] = ((wn0 + nfp * 16 + lrow) * 72 + lcol) * 2u;

    float acc[4][4][4];
#pragma unroll
    for (int a = 0; a < 4; a++)
#pragma unroll
        for (int c = 0; c < 4; c++)
#pragma unroll
            for (int e = 0; e < 4; e++) acc[a][c][e] = 0.f;

    stage(0, 0);
    const int NK = 10;
    for (int ki = 0; ki < NK; ki++) {
        int cur = ki & 1;
        if (ki + 1 < NK) { stage(ki + 1, cur ^ 1); cp_wait1(); } else { cp_wait0(); }
        __syncthreads();
        uint32_t bA = sb + offA[cur], bB = sb + offB[cur];
#pragma unroll
        for (int kk = 0; kk < 64; kk += 16) {
            uint32_t af[4][4], bbf[2][4];
#pragma unroll
            for (int mf = 0; mf < 4; mf++) ldsm4(af[mf], bA + aoff[mf] + kk * 2);
#pragma unroll
            for (int nfp = 0; nfp < 2; nfp++) ldsm4(bbf[nfp], bB + boff[nfp] + kk * 2);
#pragma unroll
            for (int nf = 0; nf < 4; nf++) {
                uint32_t b0 = bbf[nf >> 1][nf & 1], b1 = bbf[nf >> 1][2 + (nf & 1)];
#pragma unroll
                for (int mf = 0; mf < 4; mf++) mma16(acc[mf][nf], af[mf], b0, b1);
            }
        }
        __syncthreads();
    }

    // epilogue: two-pass transpose through a 64-row bounce (R11 proven)
    float* bounce = (float*)smem;
#pragma unroll
    for (int half = 0; half < 2; half++) {
        if ((wid & 1) == half) {
#pragma unroll
            for (int mf = 0; mf < 4; mf++) {
                int r = mf * 16 + grp;
#pragma unroll
                for (int nf = 0; nf < 4; nf++) {
                    int c = wn0 + nf * 8 + 2 * lt4;
                    bounce[(c + 0) * 68 + r] = acc[mf][nf][0];
                    bounce[(c + 1) * 68 + r] = acc[mf][nf][1];
                    bounce[(c + 0) * 68 + r + 8] = acc[mf][nf][2];
                    bounce[(c + 1) * 68 + r + 8] = acc[mf][nf][3];
                }
            }
        }
        __syncthreads();
#pragma unroll
        for (int pass = 0; pass < 8; pass++) {
            int c = pass * 16 + (tid >> 4);
            int sl = (tid & 15) * 4;
            int cg = n0 + c;
            float4 v = *(const float4*)&bounce[c * 68 + sl];
            size_t idx = ((size_t)b * 256 + cg) * 32768 + s0 + half * 64 + sl;
            float4 xv = *(const float4*)(x + idx);
            float bb2 = bo[cg];
            v.x += xv.x + bb2; v.y += xv.y + bb2; v.z += xv.z + bb2; v.w += xv.w + bb2;
            *(float4*)(out + idx) = v;
        }
        __syncthreads();
    }
}

// ---------------- launch ----------------
extern "C" void kernel_launch(void* const* d_in, const int* in_sizes, int n_in,
                              void* d_out, int out_size) {
    const float* x   = (const float*)d_in[0];
    const float* ctx = (const float*)d_in[1];
    const float* gng = (const float*)d_in[2];
    const float* gnb = (const float*)d_in[3];
    const float* lng = (const float*)d_in[4];
    const float* lnb = (const float*)d_in[5];
    const float* Wq  = (const float*)d_in[6];
    const float* Wk  = (const float*)d_in[7];
    const float* Wv  = (const float*)d_in[8];
    const float* Wo  = (const float*)d_in[9];
    const float* bo  = (const float*)d_in[10];
    float* out = (float*)d_out;

    cudaFuncSetAttribute(gemm1_fused, cudaFuncAttributeMaxDynamicSharedMemorySize, SMEM1);
    cudaFuncSetAttribute(gemm2_mma, cudaFuncAttributeMaxDynamicSharedMemorySize, SMEM2);

    xt_k<<<dim3(1024, 8, 2), dim3(32, 8)>>>(x);
    gn_final_k<<<16, 256>>>();
    ctx_ln_k<<<154, 256>>>(ctx, lng, lnb);
    kv_proj_k<<<dim3(8, 20), 256>>>(Wk, Wv);
    make_vw_k<<<dim3(NP, NB), 256>>>(Wo);
    wqt_k<<<dim3(256, 2), 256>>>(Wq, gng, gnb);
    gemm1_fused<<<512, 512, SMEM1>>>();
    gemm2_mma<<<dim3(2, 512), 256, SMEM2>>>(x, bo, out);
}